// round 5
// baseline (speedup 1.0000x reference)
#include <cuda_runtime.h>
#include <cuda_bf16.h>
#include <math.h>

// Fixed problem shapes
#define BB      16
#define HH      352
#define WW      1216
#define NN      (HH * WW)          // 428032
#define PP      100000
#define BN      (BB * NN)          // 6848512
#define TYPEIND 5
#define MAXD    40.0f

#define WPB     (NN / 32)          // 13376 selector words per batch
#define WORDS   (BB * WPB)         // 214016 words total
#define TPB     64                 // tiles per batch
#define TILE_W  (WPB / TPB)        // 209 words per tile
#define NTILES  (BB * TPB)         // 1024 tiles total

// Static scratch (no runtime allocation allowed)
__device__ int      d_inv[NN];            // inverse permutation
__device__ unsigned d_permbits[WORDS];    // selector bits in PERMUTED order
__device__ int      d_tileCnt[NTILES];
__device__ int      d_tileOff[NTILES];
__device__ int      d_valid[BB];
__device__ int      d_offset[BB];
__device__ int2     d_cd[BN];             // {global lind, depth bits} compacted

// ---------------------------------------------------------------------------
// K1: inverse permutation + zero bit array + zero tile counters.
// ---------------------------------------------------------------------------
__global__ void k_prep(const int* __restrict__ perm) {
    int gid = blockIdx.x * blockDim.x + threadIdx.x;
    if (gid < WORDS)  d_permbits[gid] = 0u;
    if (gid < NTILES) d_tileCnt[gid] = 0;
    if (gid < NN)     d_inv[perm[gid]] = gid;
}

// ---------------------------------------------------------------------------
// K2: stream labels (always); load depth quad ONLY if some label==5 in it.
// Selected pixels set their permuted bit + bump their tile counter.
// ---------------------------------------------------------------------------
__global__ void k_select(const int* __restrict__ label,
                         const float* __restrict__ depth) {
    int t   = blockIdx.x * blockDim.x + threadIdx.x;
    int gid = t * 4;                              // BN divisible by 4
    int4 lab = *reinterpret_cast<const int4*>(label + gid);

    bool any = (lab.x == TYPEIND) | (lab.y == TYPEIND) |
               (lab.z == TYPEIND) | (lab.w == TYPEIND);
    if (!any) return;

    float4 dep = *reinterpret_cast<const float4*>(depth + gid);

    int b       = gid / NN;                       // NN % 4 == 0
    int pixBase = gid - b * NN;
    unsigned* pb = d_permbits + b * WPB;
    int*      tc = d_tileCnt + b * TPB;

    int labs[4]   = {lab.x, lab.y, lab.z, lab.w};
    float deps[4] = {dep.x, dep.y, dep.z, dep.w};
#pragma unroll
    for (int k = 0; k < 4; k++) {
        if (labs[k] == TYPEIND && deps[k] < MAXD) {
            int j = d_inv[pixBase + k];
            atomicOr(&pb[j >> 5], 1u << (j & 31));
            atomicAdd(&tc[(j >> 5) / TILE_W], 1);
        }
    }
}

// ---------------------------------------------------------------------------
// K3: exclusive scan of 1024 tile counts (shfl hierarchical, 3 barriers)
//     + per-batch valid/offset.
// ---------------------------------------------------------------------------
__global__ void k_scan() {
    int t    = threadIdx.x;
    int lane = t & 31, wid = t >> 5;
    int v = d_tileCnt[t];

    // warp inclusive scan
    int inc = v;
#pragma unroll
    for (int off = 1; off < 32; off <<= 1) {
        int n = __shfl_up_sync(0xffffffffu, inc, off);
        if (lane >= off) inc += n;
    }
    __shared__ int wsum[32];
    __shared__ int wpre[32];
    __shared__ int sTotal;
    if (lane == 31) wsum[wid] = inc;
    __syncthreads();
    if (wid == 0) {
        int wv = wsum[lane];
        int wi = wv;
#pragma unroll
        for (int off = 1; off < 32; off <<= 1) {
            int n = __shfl_up_sync(0xffffffffu, wi, off);
            if (lane >= off) wi += n;
        }
        wpre[lane] = wi - wv;                     // exclusive warp prefix
        if (lane == 31) sTotal = wi;              // grand total
    }
    __syncthreads();
    d_tileOff[t] = inc + wpre[wid] - v;           // exclusive scan result
    __syncthreads();
    if (t < BB) {
        int off_b = d_tileOff[t * TPB];
        int nxt   = (t == BB - 1) ? sTotal : d_tileOff[(t + 1) * TPB];
        d_offset[t] = off_b;
        d_valid[t]  = nxt - off_b;
    }
}

// ---------------------------------------------------------------------------
// K4: order-preserving compaction. grid = NTILES x 256, one word per thread.
// ---------------------------------------------------------------------------
__global__ void k_compact(const int* __restrict__ perm,
                          const float* __restrict__ depth) {
    int blk  = blockIdx.x;
    int t    = threadIdx.x;
    int lane = t & 31, wid = t >> 5;

    int b       = blk / TPB;
    int wbatch0 = (blk - b * TPB) * TILE_W;
    int bn      = b * NN;

    unsigned bits = 0;
    if (t < TILE_W) bits = d_permbits[b * WPB + wbatch0 + t];
    int c = __popc(bits);

    int inc = c;
#pragma unroll
    for (int off = 1; off < 32; off <<= 1) {
        int n = __shfl_up_sync(0xffffffffu, inc, off);
        if (lane >= off) inc += n;
    }
    __shared__ int ws[8];
    if (lane == 31) ws[wid] = inc;
    __syncthreads();
    int wbase = 0;
#pragma unroll
    for (int w = 0; w < 8; w++) if (w < wid) wbase += ws[w];

    int slot = d_tileOff[blk] + wbase + inc - c;

    if (bits) {
        int jbase = (wbatch0 + t) * 32;
        while (bits) {
            int l = __ffs(bits) - 1;
            bits &= bits - 1;
            int pix = __ldg(perm + jbase + l);
            int val = bn + pix;
            float dv = __ldg(depth + val);
            d_cd[slot] = make_int2(val, __float_as_int(dv));
            slot++;
        }
    }
}

// ---------------------------------------------------------------------------
// K5: sample + back-project; write [B,3,P] points then [B] indicator.
// ---------------------------------------------------------------------------
__global__ void k_output(const float* __restrict__ invK,
                         const float* __restrict__ bind,
                         float* __restrict__ out) {
    int i = blockIdx.x * blockDim.x + threadIdx.x;
    if (i < BB)
        out[3 * BB * PP + i] = (d_valid[i] > 0) ? 1.0f : 0.0f;
    if (i >= BB * PP) return;

    int b = i / PP;
    int p = i - b * PP;
    int vn = d_valid[b];

    int idx = 0;
    if (vn > 0)
        idx = (int)fmodf(bind[i], (float)vn) + d_offset[b];

    int2  cd  = d_cd[idx];
    int   pos = cd.x;
    float d   = __int_as_float(cd.y);
    int bb  = pos / NN;
    int pix = pos - bb * NN;
    int q   = pix / WW;
    float y = (float)q;
    float x = (float)(pix - q * WW);
    float hx = x * d, hy = y * d;

    const float* M = invK + bb * 16;
#pragma unroll
    for (int c = 0; c < 3; c++) {
        float v = fmaf(__ldg(&M[c * 4 + 0]), hx,
                  fmaf(__ldg(&M[c * 4 + 1]), hy,
                  fmaf(__ldg(&M[c * 4 + 2]), d, __ldg(&M[c * 4 + 3]))));
        out[(b * 3 + c) * PP + p] = v;
    }
}

// ---------------------------------------------------------------------------
extern "C" void kernel_launch(void* const* d_in, const int* in_sizes, int n_in,
                              void* d_out, int out_size) {
    const float* predDepth = (const float*)d_in[0];   // [B,1,H,W]
    const float* invcamK   = (const float*)d_in[1];   // [B,4,4]
    const int*   semLabel  = (const int*)  d_in[2];   // [B,1,H,W]
    const float* bind      = (const float*)d_in[3];   // [B,P]
    const int*   perm      = (const int*)  d_in[4];   // [N]
    float* out = (float*)d_out;

    k_prep   <<<NN / 256, 256>>>(perm);
    k_select <<<BN / 1024, 256>>>(semLabel, predDepth);
    k_scan   <<<1, 1024>>>();
    k_compact<<<NTILES, 256>>>(perm, predDepth);
    k_output <<<(BB * PP) / 256, 256>>>(invcamK, bind, out);
}

// round 6
// speedup vs baseline: 1.4675x; 1.4675x over previous
#include <cuda_runtime.h>
#include <cuda_bf16.h>
#include <math.h>

// Fixed problem shapes
#define BB      16
#define HH      352
#define WW      1216
#define NN      (HH * WW)          // 428032
#define PP      100000
#define BN      (BB * NN)          // 6848512
#define TYPEIND 5
#define MAXD    40.0f

#define WPB     (NN / 32)          // 13376 selector words per batch
#define WORDS   (BB * WPB)         // 214016 words total
#define TPB     64                 // tiles per batch
#define TILE_W  (WPB / TPB)        // 209 words per tile
#define NTILES  (BB * TPB)         // 1024 tiles total

// Static scratch (no runtime allocation allowed)
__device__ int      d_inv[NN];            // inverse permutation
__device__ unsigned d_permbits[WORDS];    // selector bits in PERMUTED order
__device__ int      d_tileCnt[NTILES];
__device__ int      d_tileOff[NTILES];
__device__ int      d_valid[BB];
__device__ int      d_offset[BB];
__device__ int2     d_cd[BN];             // {global lind, depth bits} compacted

// ---------------------------------------------------------------------------
// K1: build inverse permutation; zero the bit array.
// ---------------------------------------------------------------------------
__global__ void k_prep(const int* __restrict__ perm) {
    int gid = blockIdx.x * blockDim.x + threadIdx.x;
    if (gid < WORDS) d_permbits[gid] = 0u;
    if (gid < NN)    d_inv[perm[gid]] = gid;
}

// ---------------------------------------------------------------------------
// K2: stream selector over all pixels (vectorized x4, unconditional loads
// to keep MLP=2). Selected pixels (~2.6%) set their permuted bit.
// ---------------------------------------------------------------------------
__global__ void k_select(const int* __restrict__ label,
                         const float* __restrict__ depth) {
    int t   = blockIdx.x * blockDim.x + threadIdx.x;
    int gid = t * 4;                              // BN divisible by 4
    int4   lab = *reinterpret_cast<const int4*>(label + gid);
    float4 dep = *reinterpret_cast<const float4*>(depth + gid);

    int b       = gid / NN;                       // NN % 4 == 0
    int pixBase = gid - b * NN;
    unsigned* pb = d_permbits + b * WPB;

    int labs[4]   = {lab.x, lab.y, lab.z, lab.w};
    float deps[4] = {dep.x, dep.y, dep.z, dep.w};
#pragma unroll
    for (int k = 0; k < 4; k++) {
        if (labs[k] == TYPEIND && deps[k] < MAXD) {
            int j = d_inv[pixBase + k];
            atomicOr(&pb[j >> 5], 1u << (j & 31));
        }
    }
}

// ---------------------------------------------------------------------------
// K3: per-tile popcount. grid = NTILES x 128 threads (209 words/tile).
// ---------------------------------------------------------------------------
__global__ void k_count() {
    int blk = blockIdx.x;
    int t   = threadIdx.x;
    const unsigned* w = d_permbits + blk * TILE_W;
    int c = 0;
    if (t < TILE_W)       c += __popc(w[t]);
    if (t + 128 < TILE_W) c += __popc(w[t + 128]);
#pragma unroll
    for (int off = 16; off; off >>= 1)
        c += __shfl_down_sync(0xffffffffu, c, off);
    __shared__ int ws[4];
    if ((t & 31) == 0) ws[t >> 5] = c;
    __syncthreads();
    if (t == 0) d_tileCnt[blk] = ws[0] + ws[1] + ws[2] + ws[3];
}

// ---------------------------------------------------------------------------
// K4: exclusive scan of 1024 tile counts (shfl hierarchical, 3 barriers)
//     + per-batch valid/offset.
// ---------------------------------------------------------------------------
__global__ void k_scan() {
    int t    = threadIdx.x;
    int lane = t & 31, wid = t >> 5;
    int v = d_tileCnt[t];

    int inc = v;
#pragma unroll
    for (int off = 1; off < 32; off <<= 1) {
        int n = __shfl_up_sync(0xffffffffu, inc, off);
        if (lane >= off) inc += n;
    }
    __shared__ int wsum[32];
    __shared__ int wpre[32];
    __shared__ int sTotal;
    if (lane == 31) wsum[wid] = inc;
    __syncthreads();
    if (wid == 0) {
        int wv = wsum[lane];
        int wi = wv;
#pragma unroll
        for (int off = 1; off < 32; off <<= 1) {
            int n = __shfl_up_sync(0xffffffffu, wi, off);
            if (lane >= off) wi += n;
        }
        wpre[lane] = wi - wv;                     // exclusive warp prefix
        if (lane == 31) sTotal = wi;              // grand total
    }
    __syncthreads();
    d_tileOff[t] = inc + wpre[wid] - v;           // exclusive scan result
    __syncthreads();
    if (t < BB) {
        int off_b = d_tileOff[t * TPB];
        int nxt   = (t == BB - 1) ? sTotal : d_tileOff[(t + 1) * TPB];
        d_offset[t] = off_b;
        d_valid[t]  = nxt - off_b;
    }
}

// ---------------------------------------------------------------------------
// K5: order-preserving compaction. grid = NTILES x 256, one word per thread.
// ---------------------------------------------------------------------------
__global__ void k_compact(const int* __restrict__ perm,
                          const float* __restrict__ depth) {
    int blk  = blockIdx.x;
    int t    = threadIdx.x;
    int lane = t & 31, wid = t >> 5;

    int b       = blk / TPB;
    int wbatch0 = (blk - b * TPB) * TILE_W;
    int bn      = b * NN;

    unsigned bits = 0;
    if (t < TILE_W) bits = d_permbits[b * WPB + wbatch0 + t];
    int c = __popc(bits);

    int inc = c;
#pragma unroll
    for (int off = 1; off < 32; off <<= 1) {
        int n = __shfl_up_sync(0xffffffffu, inc, off);
        if (lane >= off) inc += n;
    }
    __shared__ int ws[8];
    if (lane == 31) ws[wid] = inc;
    __syncthreads();
    int wbase = 0;
#pragma unroll
    for (int w = 0; w < 8; w++) if (w < wid) wbase += ws[w];

    int slot = d_tileOff[blk] + wbase + inc - c;

    if (bits) {
        int jbase = (wbatch0 + t) * 32;
        // phase 1: gather all perm values (independent loads, MLP)
        int pixv[16];
        int cnt = 0;
        unsigned bb2 = bits;
        while (bb2 && cnt < 16) {
            int l = __ffs(bb2) - 1;
            bb2 &= bb2 - 1;
            pixv[cnt++] = __ldg(perm + jbase + l);
        }
        // phase 2: gather depths (independent), then store int2 pairs
#pragma unroll 4
        for (int k = 0; k < cnt; k++) {
            int val = bn + pixv[k];
            float dv = __ldg(depth + val);
            d_cd[slot + k] = make_int2(val, __float_as_int(dv));
        }
        // rare overflow path (>16 set bits in one word)
        if (bb2) {
            int s2 = slot + cnt;
            while (bb2) {
                int l = __ffs(bb2) - 1;
                bb2 &= bb2 - 1;
                int pix = __ldg(perm + jbase + l);
                int val = bn + pix;
                float dv = __ldg(depth + val);
                d_cd[s2++] = make_int2(val, __float_as_int(dv));
            }
        }
    }
}

// ---------------------------------------------------------------------------
// K6: sample + back-project; write [B,3,P] points then [B] indicator.
// ---------------------------------------------------------------------------
__global__ void k_output(const float* __restrict__ invK,
                         const float* __restrict__ bind,
                         float* __restrict__ out) {
    int i = blockIdx.x * blockDim.x + threadIdx.x;
    if (i < BB)
        out[3 * BB * PP + i] = (d_valid[i] > 0) ? 1.0f : 0.0f;
    if (i >= BB * PP) return;

    int b = i / PP;
    int p = i - b * PP;
    int vn = d_valid[b];

    int idx = 0;
    if (vn > 0)
        idx = (int)fmodf(bind[i], (float)vn) + d_offset[b];

    int2  cd  = d_cd[idx];
    int   pos = cd.x;
    float d   = __int_as_float(cd.y);
    int bb  = pos / NN;
    int pix = pos - bb * NN;
    int q   = pix / WW;
    float y = (float)q;
    float x = (float)(pix - q * WW);
    float hx = x * d, hy = y * d;

    const float* M = invK + bb * 16;
#pragma unroll
    for (int c = 0; c < 3; c++) {
        float v = fmaf(__ldg(&M[c * 4 + 0]), hx,
                  fmaf(__ldg(&M[c * 4 + 1]), hy,
                  fmaf(__ldg(&M[c * 4 + 2]), d, __ldg(&M[c * 4 + 3]))));
        out[(b * 3 + c) * PP + p] = v;
    }
}

// ---------------------------------------------------------------------------
extern "C" void kernel_launch(void* const* d_in, const int* in_sizes, int n_in,
                              void* d_out, int out_size) {
    const float* predDepth = (const float*)d_in[0];   // [B,1,H,W]
    const float* invcamK   = (const float*)d_in[1];   // [B,4,4]
    const int*   semLabel  = (const int*)  d_in[2];   // [B,1,H,W]
    const float* bind      = (const float*)d_in[3];   // [B,P]
    const int*   perm      = (const int*)  d_in[4];   // [N]
    float* out = (float*)d_out;

    k_prep   <<<NN / 256, 256>>>(perm);
    k_select <<<BN / 1024, 256>>>(semLabel, predDepth);
    k_count  <<<NTILES, 128>>>();
    k_scan   <<<1, 1024>>>();
    k_compact<<<NTILES, 256>>>(perm, predDepth);
    k_output <<<(BB * PP) / 256, 256>>>(invcamK, bind, out);
}